// round 2
// baseline (speedup 1.0000x reference)
#include <cuda_runtime.h>
#include <cuda_bf16.h>
#include <math.h>

// ---------------- problem constants ----------------
#define BB      32
#define CIN     3
#define HIN     32
#define C0      256
#define KSZ     4
#define H1      29            // 32-4+1
#define H2      13            // (29-4)/2+1
#define SP2     (H2*H2)       // 169
#define NCAP    16
#define NCLS    10
#define OD      4
#define ROUTES  (C0*SP2)      // 43264
#define MM      (BB*SP2)      // 5408
#define NN      (NCAP*C0)     // 4096
#define KD      (C0*KSZ*KSZ)  // 4096
#define RCH     26            // routing reduction chunks per batch

// ---------------- scratch (device globals; no allocs) ----------------
__device__ float g_h[BB*C0*H1*H1];                  // 27.6 MB   stem output
__device__ float g_patch[(size_t)MM*KD];            // 88.6 MB   im2col
__device__ float g_p[(size_t)MM*NN];                // 88.6 MB   gemm output
__device__ float g_u[(size_t)BB*ROUTES*NCAP];       // 88.6 MB   squashed primary caps
__device__ float g_uhat[(size_t)BB*ROUTES*NCLS*OD]; // 221.5 MB
__device__ float g_part[BB*RCH*NCLS*OD];            // partial routing sums
__device__ float g_A[BB*NCLS*OD];                   // accumulated v (routing state)

// ---------------- stem conv + relu ----------------
// grid (256 oc, 32 b), 256 threads
__global__ void conv1_kernel(const float* __restrict__ x,
                             const float* __restrict__ w,
                             const float* __restrict__ bias) {
    __shared__ float xs[CIN*HIN*HIN];   // 3072
    __shared__ float ws[CIN*KSZ*KSZ];   // 48
    const int oc = blockIdx.x;
    const int b  = blockIdx.y;
    const int tid = threadIdx.x;
    for (int i = tid; i < CIN*HIN*HIN; i += 256) xs[i] = x[b*CIN*HIN*HIN + i];
    if (tid < 48) ws[tid] = w[oc*48 + tid];
    __syncthreads();
    const float bv = bias[oc];
    for (int pos = tid; pos < H1*H1; pos += 256) {
        const int oy = pos / H1, ox = pos % H1;
        float acc = bv;
        #pragma unroll
        for (int c = 0; c < 3; ++c)
            #pragma unroll
            for (int ky = 0; ky < 4; ++ky)
                #pragma unroll
                for (int kx = 0; kx < 4; ++kx)
                    acc += xs[c*HIN*HIN + (oy+ky)*HIN + (ox+kx)] * ws[c*16 + ky*4 + kx];
        g_h[((size_t)(b*C0 + oc)*H1 + oy)*H1 + ox] = fmaxf(acc, 0.0f);
    }
}

// ---------------- im2col (stride-2, k=4) ----------------
__global__ void im2col_kernel() {
    const int idx = blockIdx.x * 256 + threadIdx.x;   // MM*KD = 22,151,168 exact
    const int m = idx >> 12;        // /4096
    const int k = idx & 4095;
    const int b = m / SP2, sp = m % SP2;
    const int oy = sp / H2, ox = sp % H2;
    const int c = k >> 4;
    const int r = k & 15;
    const int ky = r >> 2, kx = r & 3;
    g_patch[idx] = g_h[((size_t)(b*C0 + c)*H1 + (2*oy + ky))*H1 + (2*ox + kx)];
}

// ---------------- SGEMM: g_p[M,N] = g_patch[M,K] * Wc[N,K]^T + bias ----------------
// 128x128x8 tile, 8x8 microtile, smem double buffered. grid (N/128=32, ceil(M/128)=43)
__global__ void __launch_bounds__(256, 2)
gemm_kernel(const float* __restrict__ Wc, const float* __restrict__ bias) {
    __shared__ float As[2][8][128];
    __shared__ float Bs[2][8][128];
    const int tid = threadIdx.x;
    const int bn = blockIdx.x * 128;
    const int bm = blockIdx.y * 128;
    const int lr = tid & 127;            // row within tile for loads
    const int lk = (tid >> 7) << 2;      // 0 or 4 (k offset)
    const int tx = tid & 15;
    const int ty = tid >> 4;

    const int am = bm + lr;
    const bool am_ok = (am < MM);
    const float* Arow = g_patch + (size_t)(am_ok ? am : 0) * KD + lk;
    const float* Brow = Wc + (size_t)(bn + lr) * KD + lk;

    float4 pa = am_ok ? __ldg((const float4*)Arow) : make_float4(0.f,0.f,0.f,0.f);
    float4 pb = __ldg((const float4*)Brow);
    As[0][lk+0][lr]=pa.x; As[0][lk+1][lr]=pa.y; As[0][lk+2][lr]=pa.z; As[0][lk+3][lr]=pa.w;
    Bs[0][lk+0][lr]=pb.x; Bs[0][lk+1][lr]=pb.y; Bs[0][lk+2][lr]=pb.z; Bs[0][lk+3][lr]=pb.w;
    __syncthreads();

    float acc[8][8];
    #pragma unroll
    for (int i = 0; i < 8; ++i)
        #pragma unroll
        for (int j = 0; j < 8; ++j) acc[i][j] = 0.f;

    int cur = 0;
    const int NT = KD / 8;   // 512
    for (int t = 0; t < NT; ++t) {
        if (t + 1 < NT) {
            pa = am_ok ? __ldg((const float4*)(Arow + (size_t)(t+1)*8)) : make_float4(0.f,0.f,0.f,0.f);
            pb = __ldg((const float4*)(Brow + (size_t)(t+1)*8));
        }
        #pragma unroll
        for (int k = 0; k < 8; ++k) {
            float a[8], b[8];
            *(float4*)&a[0] = *(const float4*)&As[cur][k][ty*8];
            *(float4*)&a[4] = *(const float4*)&As[cur][k][ty*8+4];
            *(float4*)&b[0] = *(const float4*)&Bs[cur][k][tx*8];
            *(float4*)&b[4] = *(const float4*)&Bs[cur][k][tx*8+4];
            #pragma unroll
            for (int i = 0; i < 8; ++i)
                #pragma unroll
                for (int j = 0; j < 8; ++j)
                    acc[i][j] += a[i] * b[j];
        }
        if (t + 1 < NT) {
            const int nb = cur ^ 1;
            As[nb][lk+0][lr]=pa.x; As[nb][lk+1][lr]=pa.y; As[nb][lk+2][lr]=pa.z; As[nb][lk+3][lr]=pa.w;
            Bs[nb][lk+0][lr]=pb.x; Bs[nb][lk+1][lr]=pb.y; Bs[nb][lk+2][lr]=pb.z; Bs[nb][lk+3][lr]=pb.w;
            __syncthreads();
            cur = nb;
        }
    }

    float bv[8];
    #pragma unroll
    for (int j = 0; j < 8; ++j) bv[j] = bias[bn + tx*8 + j];
    #pragma unroll
    for (int i = 0; i < 8; ++i) {
        const int row = bm + ty*8 + i;
        if (row < MM) {
            float4 o0 = make_float4(acc[i][0]+bv[0], acc[i][1]+bv[1], acc[i][2]+bv[2], acc[i][3]+bv[3]);
            float4 o1 = make_float4(acc[i][4]+bv[4], acc[i][5]+bv[5], acc[i][6]+bv[6], acc[i][7]+bv[7]);
            *(float4*)&g_p[(size_t)row*NN + bn + tx*8]     = o0;
            *(float4*)&g_p[(size_t)row*NN + bn + tx*8 + 4] = o1;
        }
    }
}

// ---------------- squash over the 16 capsule dims -> g_u[b][j][i] ----------------
// one warp per (b, sp, c0-group-of-32); 43264 warps total -> 5408 blocks @ 8 warps
__global__ void squash_kernel() {
    const int warp = (blockIdx.x * 256 + threadIdx.x) >> 5;
    const int lane = threadIdx.x & 31;
    const int b   = warp / (SP2 * 8);
    const int rem = warp % (SP2 * 8);
    const int sp  = rem / 8;
    const int c0  = (rem % 8) * 32 + lane;
    const int m   = b * SP2 + sp;
    float v[NCAP];
    float n2 = 0.f;
    #pragma unroll
    for (int i = 0; i < NCAP; ++i) {
        v[i] = g_p[(size_t)m*NN + i*C0 + c0];
        n2 += v[i]*v[i];
    }
    const float sc = (n2 / (1.f + n2)) * rsqrtf(n2 + 1e-8f);
    const size_t base = ((size_t)b*ROUTES + (size_t)c0*SP2 + sp) * NCAP;
    #pragma unroll
    for (int i = 0; i < NCAP; ++i) g_u[base + i] = v[i] * sc;
}

// ---------------- u_hat[b,j,c,o] = sum_i route_W[j,c,o,i] * u[b,j,i] ----------------
// one block per route j; W block (640 f) cached in smem, reused across all 32 b
__global__ void uhat_kernel(const float* __restrict__ rW) {
    __shared__ float Ws[NCLS*OD*NCAP];  // 640
    __shared__ float us[BB][NCAP];      // 512
    const int j = blockIdx.x;
    const int tid = threadIdx.x;
    for (int i = tid; i < 640; i += 256) Ws[i] = rW[(size_t)j*640 + i];
    for (int i = tid; i < BB*NCAP; i += 256) {
        const int b = i >> 4, ii = i & 15;
        us[b][ii] = g_u[((size_t)b*ROUTES + j)*NCAP + ii];
    }
    __syncthreads();
    #pragma unroll
    for (int r = 0; r < 5; ++r) {
        const int idx = tid + 256*r;     // < 1280 exactly
        const int b = idx / 40, co = idx % 40;
        float acc = 0.f;
        #pragma unroll
        for (int i = 0; i < NCAP; ++i) acc += Ws[co*NCAP + i] * us[b][i];
        g_uhat[((size_t)b*ROUTES + j)*40 + co] = acc;
    }
}

__global__ void init_kernel() {
    const int i = blockIdx.x*256 + threadIdx.x;
    if (i < BB*NCLS*OD) g_A[i] = 0.f;
}

// ---------------- one routing iteration: streaming pass over u_hat ----------------
// b_log[b,j,c] == u_hat[b,j,c,:] . A[b,c,:]  (linearity of the logit update)
// grid (b=32, chunk=RCH), 256 threads; deterministic chunked partials (no atomics)
__global__ void route_reduce_kernel() {
    __shared__ float4 Ash[NCLS];
    __shared__ float red[8][40];
    const int b = blockIdx.x;
    const int tid = threadIdx.x;
    if (tid < NCLS) Ash[tid] = *(const float4*)&g_A[b*40 + tid*4];
    __syncthreads();

    float4 acc4[NCLS];
    #pragma unroll
    for (int c = 0; c < NCLS; ++c) acc4[c] = make_float4(0.f,0.f,0.f,0.f);

    for (int j = blockIdx.y*256 + tid; j < ROUTES; j += RCH*256) {
        const float4* uh4 = (const float4*)(g_uhat + ((size_t)b*ROUTES + j)*40);
        float4 q[NCLS];
        float logit[NCLS];
        float mx = -1e30f;
        #pragma unroll
        for (int c = 0; c < NCLS; ++c) {
            q[c] = uh4[c];
            const float4 a = Ash[c];
            const float l = q[c].x*a.x + q[c].y*a.y + q[c].z*a.z + q[c].w*a.w;
            logit[c] = l;
            mx = fmaxf(mx, l);
        }
        float se = 0.f;
        #pragma unroll
        for (int c = 0; c < NCLS; ++c) { logit[c] = __expf(logit[c] - mx); se += logit[c]; }
        const float inv = 1.f / se;
        #pragma unroll
        for (int c = 0; c < NCLS; ++c) {
            const float cc = logit[c] * inv;
            acc4[c].x += cc*q[c].x; acc4[c].y += cc*q[c].y;
            acc4[c].z += cc*q[c].z; acc4[c].w += cc*q[c].w;
        }
    }

    const int lane = tid & 31, w = tid >> 5;
    #pragma unroll
    for (int c = 0; c < NCLS; ++c) {
        float4 v = acc4[c];
        #pragma unroll
        for (int off = 16; off; off >>= 1) {
            v.x += __shfl_down_sync(0xffffffffu, v.x, off);
            v.y += __shfl_down_sync(0xffffffffu, v.y, off);
            v.z += __shfl_down_sync(0xffffffffu, v.z, off);
            v.w += __shfl_down_sync(0xffffffffu, v.w, off);
        }
        if (lane == 0) {
            red[w][c*4+0] = v.x; red[w][c*4+1] = v.y;
            red[w][c*4+2] = v.z; red[w][c*4+3] = v.w;
        }
    }
    __syncthreads();
    if (tid < 40) {
        float s = 0.f;
        #pragma unroll
        for (int w2 = 0; w2 < 8; ++w2) s += red[w2][tid];
        g_part[((size_t)b*RCH + blockIdx.y)*40 + tid] = s;
    }
}

// ---------------- finalize: s -> v = squash(s); A += v; last iter -> output ----------------
__global__ void finalize_kernel(float* __restrict__ out, int last) {
    __shared__ float len[BB*NCLS];
    const int tid = threadIdx.x;  // 512
    if (tid < BB*NCLS) {
        const int c = tid % NCLS;
        float s0=0.f, s1=0.f, s2=0.f, s3=0.f;
        const int b = tid / NCLS;
        for (int ch = 0; ch < RCH; ++ch) {
            const float* pp = &g_part[((size_t)b*RCH + ch)*40 + c*4];
            s0 += pp[0]; s1 += pp[1]; s2 += pp[2]; s3 += pp[3];
        }
        const float n2 = s0*s0 + s1*s1 + s2*s2 + s3*s3;
        const float sc = (n2 / (1.f + n2)) * rsqrtf(n2 + 1e-8f);
        const float v0 = s0*sc, v1 = s1*sc, v2 = s2*sc, v3 = s3*sc;
        g_A[tid*4+0] += v0; g_A[tid*4+1] += v1;
        g_A[tid*4+2] += v2; g_A[tid*4+3] += v3;
        len[tid] = sqrtf(v0*v0 + v1*v1 + v2*v2 + v3*v3);
    }
    __syncthreads();
    if (last && tid < BB) {
        float mx = -1e30f;
        #pragma unroll
        for (int c = 0; c < NCLS; ++c) mx = fmaxf(mx, len[tid*NCLS + c]);
        float e[NCLS]; float se = 0.f;
        #pragma unroll
        for (int c = 0; c < NCLS; ++c) { e[c] = __expf(len[tid*NCLS + c] - mx); se += e[c]; }
        const float inv = 1.f / se;
        #pragma unroll
        for (int c = 0; c < NCLS; ++c) out[tid*NCLS + c] = e[c] * inv;
    }
}

// ---------------- launch ----------------
extern "C" void kernel_launch(void* const* d_in, const int* in_sizes, int n_in,
                              void* d_out, int out_size) {
    const float* x        = (const float*)d_in[0];
    const float* conv_w   = (const float*)d_in[1];
    const float* conv_b   = (const float*)d_in[2];
    const float* pcaps_w  = (const float*)d_in[3];
    const float* pcaps_b  = (const float*)d_in[4];
    const float* route_W  = (const float*)d_in[5];
    float* out = (float*)d_out;

    conv1_kernel<<<dim3(C0, BB), 256>>>(x, conv_w, conv_b);
    im2col_kernel<<<(MM*KD)/256, 256>>>();
    gemm_kernel<<<dim3(NN/128, (MM + 127)/128), 256>>>(pcaps_w, pcaps_b);
    squash_kernel<<<5408, 256>>>();   // 43264 warps = 32b * 169sp * 8 groups
    uhat_kernel<<<ROUTES, 256>>>(route_W);
    init_kernel<<<(BB*NCLS*OD + 255)/256, 256>>>();
    for (int t = 0; t < 8; ++t) {
        route_reduce_kernel<<<dim3(BB, RCH), 256>>>();
        finalize_kernel<<<1, 512>>>(out, t == 7);
    }
}

// round 9
// speedup vs baseline: 2.1489x; 2.1489x over previous
#include <cuda_runtime.h>
#include <cuda_bf16.h>
#include <math.h>
#include <stdint.h>

// ---------------- problem constants ----------------
#define BB      32
#define CIN     3
#define HIN     32
#define C0      256
#define KSZ     4
#define H1      29            // 32-4+1
#define H2      13            // (29-4)/2+1
#define SP2     (H2*H2)       // 169
#define NCAP    16
#define NCLS    10
#define OD      4
#define ROUTES  (C0*SP2)      // 43264
#define MM      (BB*SP2)      // 5408
#define NN      (NCAP*C0)     // 4096
#define KD      (C0*KSZ*KSZ)  // 4096
#define RCH     26            // routing reduction chunks per batch

// GEMM tiling (mma.sync path, baseline ISA)
#define TM      128
#define TN      256
#define TKC     32            // bf16 K elements per chunk
#define NKC     (KD/TKC)      // 128 chunks
#define MTILES  43
#define MPAD    (MTILES*TM)   // 5504
#define NTILES  (NN/TN)       // 16
#define ASTR    40            // padded smem row stride in bf16 (80 B, ldmatrix conflict-free)
#define APL     (128*ASTR*2)  // 10240 B per A plane
#define BPL     (256*ASTR*2)  // 20480 B per B plane
#define STG     (2*APL+2*BPL) // 61440 B per stage
#define SMEMB   (2*STG)       // 122880 B dynamic smem

// ---------------- scratch (device globals; no allocs) ----------------
__device__ float g_h[BB*C0*H1*H1];                        // stem output
__device__ __nv_bfloat16 g_ah[(size_t)MPAD*KD];           // A hi plane (padded M)
__device__ __nv_bfloat16 g_al[(size_t)MPAD*KD];           // A lo plane
__device__ __nv_bfloat16 g_bh[(size_t)NN*KD];             // W hi plane
__device__ __nv_bfloat16 g_bl[(size_t)NN*KD];             // W lo plane
__device__ float g_p[(size_t)MM*NN];                      // gemm output
__device__ float g_u[(size_t)BB*ROUTES*NCAP];             // squashed primary caps
__device__ float g_uhat[(size_t)BB*ROUTES*NCLS*OD];       // prediction vectors
__device__ float g_part[BB*RCH*NCLS*OD];                  // partial routing sums
__device__ float g_A[BB*NCLS*OD];                         // accumulated v (routing state)

// ---------------- PTX helpers (baseline ISA only) ----------------
__device__ __forceinline__ uint32_t smem_u32(const void* p) {
    uint32_t a;
    asm("{ .reg .u64 t; cvta.to.shared.u64 t, %1; cvt.u32.u64 %0, t; }" : "=r"(a) : "l"(p));
    return a;
}
__device__ __forceinline__ void cp16(uint32_t s, const void* g) {
    asm volatile("cp.async.cg.shared.global [%0], [%1], 16;" :: "r"(s), "l"(g));
}
__device__ __forceinline__ void ldm4(uint32_t* r, uint32_t addr) {
    asm volatile("ldmatrix.sync.aligned.m8n8.x4.shared.b16 {%0,%1,%2,%3}, [%4];"
        : "=r"(r[0]), "=r"(r[1]), "=r"(r[2]), "=r"(r[3]) : "r"(addr));
}
__device__ __forceinline__ void mma16816(float* c, const uint32_t* a, const uint32_t* b) {
    asm volatile("mma.sync.aligned.m16n8k16.row.col.f32.bf16.bf16.f32 "
        "{%0,%1,%2,%3}, {%4,%5,%6,%7}, {%8,%9}, {%0,%1,%2,%3};"
        : "+f"(c[0]), "+f"(c[1]), "+f"(c[2]), "+f"(c[3])
        : "r"(a[0]), "r"(a[1]), "r"(a[2]), "r"(a[3]), "r"(b[0]), "r"(b[1]));
}

// ---------------- stem conv + relu ----------------
__global__ void conv1_kernel(const float* __restrict__ x,
                             const float* __restrict__ w,
                             const float* __restrict__ bias) {
    __shared__ float xs[CIN*HIN*HIN];
    __shared__ float ws[CIN*KSZ*KSZ];
    const int oc = blockIdx.x;
    const int b  = blockIdx.y;
    const int tid = threadIdx.x;
    for (int i = tid; i < CIN*HIN*HIN; i += 256) xs[i] = x[b*CIN*HIN*HIN + i];
    if (tid < 48) ws[tid] = w[oc*48 + tid];
    __syncthreads();
    const float bv = bias[oc];
    for (int pos = tid; pos < H1*H1; pos += 256) {
        const int oy = pos / H1, ox = pos % H1;
        float acc = bv;
        #pragma unroll
        for (int c = 0; c < 3; ++c)
            #pragma unroll
            for (int ky = 0; ky < 4; ++ky)
                #pragma unroll
                for (int kx = 0; kx < 4; ++kx)
                    acc += xs[c*HIN*HIN + (oy+ky)*HIN + (ox+kx)] * ws[c*16 + ky*4 + kx];
        g_h[((size_t)(b*C0 + oc)*H1 + oy)*H1 + ox] = fmaxf(acc, 0.0f);
    }
}

// ---------------- fused im2col + bf16 hi/lo split (A planes, padded M) ----------------
__global__ void im2col_split_kernel() {
    const size_t idx = (size_t)blockIdx.x * 256 + threadIdx.x;   // MPAD*KD exact multiple
    const int m = (int)(idx >> 12);
    const int k = (int)(idx & 4095);
    float v = 0.f;
    if (m < MM) {
        const int b = m / SP2, sp = m % SP2;
        const int oy = sp / H2, ox = sp % H2;
        const int c = k >> 4, r = k & 15;
        const int ky = r >> 2, kx = r & 3;
        v = g_h[((size_t)(b*C0 + c)*H1 + (2*oy + ky))*H1 + (2*ox + kx)];
    }
    const __nv_bfloat16 hi = __float2bfloat16(v);
    g_ah[idx] = hi;
    g_al[idx] = __float2bfloat16(v - __bfloat162float(hi));
}

// ---------------- weight bf16 hi/lo split ----------------
__global__ void wsplit_kernel(const float* __restrict__ Wc) {
    const size_t idx = (size_t)blockIdx.x * 256 + threadIdx.x;   // NN*KD exact
    const float v = Wc[idx];
    const __nv_bfloat16 hi = __float2bfloat16(v);
    g_bh[idx] = hi;
    g_bl[idx] = __float2bfloat16(v - __bfloat162float(hi));
}

// ---------------- bf16 mma.sync GEMM: g_p[M,N] = A[M,K]*W[N,K]^T + bias ----------------
// split-bf16 (hi*hi + lo*hi + hi*lo), fp32 accum. CTA 128x256, warp 64x64,
// K chunks of 32, 2-stage cp.async pipeline, padded-stride conflict-free smem.
__global__ void __launch_bounds__(256, 1)
mma_gemm_kernel(const float* __restrict__ bias) {
    extern __shared__ char smem[];
    const uint32_t sb = smem_u32(smem);
    const int tid = threadIdx.x;
    const int wid = tid >> 5, lane = tid & 31;
    const int bn = blockIdx.x * TN, bm = blockIdx.y * TM;
    const int wm = (wid & 1) * 64, wn = (wid >> 1) * 64;

    // ---- cp.async assignments ----
    uint32_t a_soff[2]; size_t a_goff[2];
    #pragma unroll
    for (int q = 0; q < 2; ++q) {
        const int u = q*256 + tid, row = u >> 2, ch = u & 3;
        a_soff[q] = (uint32_t)(row*(ASTR*2) + ch*16);
        a_goff[q] = ((size_t)(bm + row)*KD + ch*8) * 2;     // bytes
    }
    uint32_t b_soff[4]; size_t b_goff[4];
    #pragma unroll
    for (int q = 0; q < 4; ++q) {
        const int u = q*256 + tid, row = u >> 2, ch = u & 3;
        b_soff[q] = (uint32_t)(row*(ASTR*2) + ch*16);
        b_goff[q] = ((size_t)(bn + row)*KD + ch*8) * 2;     // bytes
    }
    const char* pah = (const char*)g_ah;
    const char* pal = (const char*)g_al;
    const char* pbh = (const char*)g_bh;
    const char* pbl = (const char*)g_bl;

    // ---- ldmatrix per-lane base offsets ----
    const int g = lane >> 3, lr = lane & 7;
    uint32_t a_lm[4];
    #pragma unroll
    for (int i = 0; i < 4; ++i) {
        const int arow = wm + i*16 + ((g & 1) << 3) + lr;
        a_lm[i] = (uint32_t)(arow*(ASTR*2) + (g >> 1)*16);
    }
    uint32_t b_lm[4];
    #pragma unroll
    for (int t = 0; t < 4; ++t) {
        const int brow = wn + t*16 + ((g >> 1) << 3) + lr;
        b_lm[t] = (uint32_t)(brow*(ASTR*2) + (g & 1)*16);
    }

    float acc[4][8][4];
    #pragma unroll
    for (int i = 0; i < 4; ++i)
        #pragma unroll
        for (int j = 0; j < 8; ++j)
            #pragma unroll
            for (int r = 0; r < 4; ++r) acc[i][j][r] = 0.f;

    // ---- prefetch chunks 0 and 1 ----
    #pragma unroll
    for (int pf = 0; pf < 2; ++pf) {
        const uint32_t st = sb + pf*STG;
        const size_t kb = (size_t)pf * (TKC*2);
        #pragma unroll
        for (int q = 0; q < 2; ++q) {
            cp16(st + a_soff[q],        pah + a_goff[q] + kb);
            cp16(st + APL + a_soff[q],  pal + a_goff[q] + kb);
        }
        #pragma unroll
        for (int q = 0; q < 4; ++q) {
            cp16(st + 2*APL + b_soff[q],       pbh + b_goff[q] + kb);
            cp16(st + 2*APL + BPL + b_soff[q], pbl + b_goff[q] + kb);
        }
        asm volatile("cp.async.commit_group;" ::: "memory");
    }

    for (int kc = 0; kc < NKC; ++kc) {
        if (kc + 2 < NKC) asm volatile("cp.async.wait_group 1;" ::: "memory");
        else              asm volatile("cp.async.wait_group 0;" ::: "memory");
        __syncthreads();

        const uint32_t st = sb + (kc & 1)*STG;
        #pragma unroll
        for (int ks = 0; ks < 2; ++ks) {
            uint32_t ah[4][4], al[4][4];
            #pragma unroll
            for (int i = 0; i < 4; ++i) ldm4(ah[i], st + a_lm[i] + ks*32);
            #pragma unroll
            for (int i = 0; i < 4; ++i) ldm4(al[i], st + APL + a_lm[i] + ks*32);
            #pragma unroll
            for (int t = 0; t < 4; ++t) {
                uint32_t bh[4], bl[4];
                ldm4(bh, st + 2*APL + b_lm[t] + ks*32);
                ldm4(bl, st + 2*APL + BPL + b_lm[t] + ks*32);
                #pragma unroll
                for (int i = 0; i < 4; ++i) {
                    mma16816(acc[i][2*t],   ah[i], bh);
                    mma16816(acc[i][2*t+1], ah[i], bh+2);
                    mma16816(acc[i][2*t],   al[i], bh);
                    mma16816(acc[i][2*t+1], al[i], bh+2);
                    mma16816(acc[i][2*t],   ah[i], bl);
                    mma16816(acc[i][2*t+1], ah[i], bl+2);
                }
            }
        }
        __syncthreads();

        if (kc + 2 < NKC) {
            const uint32_t st2 = sb + (kc & 1)*STG;   // same buffer, now free
            const size_t kb = (size_t)(kc+2) * (TKC*2);
            #pragma unroll
            for (int q = 0; q < 2; ++q) {
                cp16(st2 + a_soff[q],        pah + a_goff[q] + kb);
                cp16(st2 + APL + a_soff[q],  pal + a_goff[q] + kb);
            }
            #pragma unroll
            for (int q = 0; q < 4; ++q) {
                cp16(st2 + 2*APL + b_soff[q],       pbh + b_goff[q] + kb);
                cp16(st2 + 2*APL + BPL + b_soff[q], pbl + b_goff[q] + kb);
            }
            asm volatile("cp.async.commit_group;" ::: "memory");
        }
    }

    // ---- epilogue: bias add + store ----
    #pragma unroll
    for (int i = 0; i < 4; ++i) {
        const int r0 = bm + wm + i*16 + (lane >> 2);
        #pragma unroll
        for (int j = 0; j < 8; ++j) {
            const int col = bn + wn + j*8 + (lane & 3)*2;
            const float2 bv = *(const float2*)&bias[col];
            if (r0 < MM) {
                float2 o = make_float2(acc[i][j][0] + bv.x, acc[i][j][1] + bv.y);
                *(float2*)&g_p[(size_t)r0*NN + col] = o;
            }
            if (r0 + 8 < MM) {
                float2 o = make_float2(acc[i][j][2] + bv.x, acc[i][j][3] + bv.y);
                *(float2*)&g_p[(size_t)(r0+8)*NN + col] = o;
            }
        }
    }
}

// ---------------- squash over the 16 capsule dims -> g_u[b][j][i] ----------------
__global__ void squash_kernel() {
    const int warp = (blockIdx.x * 256 + threadIdx.x) >> 5;
    const int lane = threadIdx.x & 31;
    const int b   = warp / (SP2 * 8);
    const int rem = warp % (SP2 * 8);
    const int sp  = rem / 8;
    const int c0  = (rem % 8) * 32 + lane;
    const int m   = b * SP2 + sp;
    float v[NCAP];
    float n2 = 0.f;
    #pragma unroll
    for (int i = 0; i < NCAP; ++i) {
        v[i] = g_p[(size_t)m*NN + i*C0 + c0];
        n2 += v[i]*v[i];
    }
    const float sc = (n2 / (1.f + n2)) * rsqrtf(n2 + 1e-8f);
    const size_t base = ((size_t)b*ROUTES + (size_t)c0*SP2 + sp) * NCAP;
    #pragma unroll
    for (int i = 0; i < NCAP; ++i) g_u[base + i] = v[i] * sc;
}

// ---------------- u_hat ----------------
__global__ void uhat_kernel(const float* __restrict__ rW) {
    __shared__ float Ws[NCLS*OD*NCAP];
    __shared__ float us[BB][NCAP];
    const int j = blockIdx.x;
    const int tid = threadIdx.x;
    for (int i = tid; i < 640; i += 256) Ws[i] = rW[(size_t)j*640 + i];
    for (int i = tid; i < BB*NCAP; i += 256) {
        const int b = i >> 4, ii = i & 15;
        us[b][ii] = g_u[((size_t)b*ROUTES + j)*NCAP + ii];
    }
    __syncthreads();
    #pragma unroll
    for (int r = 0; r < 5; ++r) {
        const int idx = tid + 256*r;
        const int b = idx / 40, co = idx % 40;
        float acc = 0.f;
        #pragma unroll
        for (int i = 0; i < NCAP; ++i) acc += Ws[co*NCAP + i] * us[b][i];
        g_uhat[((size_t)b*ROUTES + j)*40 + co] = acc;
    }
}

__global__ void init_kernel() {
    const int i = blockIdx.x*256 + threadIdx.x;
    if (i < BB*NCLS*OD) g_A[i] = 0.f;
}

// ---------------- routing iteration (streaming, logits linear in accumulated v) ----------------
__global__ void route_reduce_kernel() {
    __shared__ float4 Ash[NCLS];
    __shared__ float red[8][40];
    const int b = blockIdx.x;
    const int tid = threadIdx.x;
    if (tid < NCLS) Ash[tid] = *(const float4*)&g_A[b*40 + tid*4];
    __syncthreads();

    float4 acc4[NCLS];
    #pragma unroll
    for (int c = 0; c < NCLS; ++c) acc4[c] = make_float4(0.f,0.f,0.f,0.f);

    for (int j = blockIdx.y*256 + tid; j < ROUTES; j += RCH*256) {
        const float4* uh4 = (const float4*)(g_uhat + ((size_t)b*ROUTES + j)*40);
        float4 q[NCLS];
        float logit[NCLS];
        float mx = -1e30f;
        #pragma unroll
        for (int c = 0; c < NCLS; ++c) {
            q[c] = uh4[c];
            const float4 a = Ash[c];
            const float l = q[c].x*a.x + q[c].y*a.y + q[c].z*a.z + q[c].w*a.w;
            logit[c] = l;
            mx = fmaxf(mx, l);
        }
        float se = 0.f;
        #pragma unroll
        for (int c = 0; c < NCLS; ++c) { logit[c] = __expf(logit[c] - mx); se += logit[c]; }
        const float inv = 1.f / se;
        #pragma unroll
        for (int c = 0; c < NCLS; ++c) {
            const float cc = logit[c] * inv;
            acc4[c].x += cc*q[c].x; acc4[c].y += cc*q[c].y;
            acc4[c].z += cc*q[c].z; acc4[c].w += cc*q[c].w;
        }
    }

    const int lane = tid & 31, w = tid >> 5;
    #pragma unroll
    for (int c = 0; c < NCLS; ++c) {
        float4 v = acc4[c];
        #pragma unroll
        for (int off = 16; off; off >>= 1) {
            v.x += __shfl_down_sync(0xffffffffu, v.x, off);
            v.y += __shfl_down_sync(0xffffffffu, v.y, off);
            v.z += __shfl_down_sync(0xffffffffu, v.z, off);
            v.w += __shfl_down_sync(0xffffffffu, v.w, off);
        }
        if (lane == 0) {
            red[w][c*4+0] = v.x; red[w][c*4+1] = v.y;
            red[w][c*4+2] = v.z; red[w][c*4+3] = v.w;
        }
    }
    __syncthreads();
    if (tid < 40) {
        float s = 0.f;
        #pragma unroll
        for (int w2 = 0; w2 < 8; ++w2) s += red[w2][tid];
        g_part[((size_t)b*RCH + blockIdx.y)*40 + tid] = s;
    }
}

// ---------------- finalize ----------------
__global__ void finalize_kernel(float* __restrict__ out, int last) {
    __shared__ float len[BB*NCLS];
    const int tid = threadIdx.x;  // 512
    if (tid < BB*NCLS) {
        const int c = tid % NCLS;
        float s0=0.f, s1=0.f, s2=0.f, s3=0.f;
        const int b = tid / NCLS;
        for (int ch = 0; ch < RCH; ++ch) {
            const float* pp = &g_part[((size_t)b*RCH + ch)*40 + c*4];
            s0 += pp[0]; s1 += pp[1]; s2 += pp[2]; s3 += pp[3];
        }
        const float n2 = s0*s0 + s1*s1 + s2*s2 + s3*s3;
        const float sc = (n2 / (1.f + n2)) * rsqrtf(n2 + 1e-8f);
        const float v0 = s0*sc, v1 = s1*sc, v2 = s2*sc, v3 = s3*sc;
        g_A[tid*4+0] += v0; g_A[tid*4+1] += v1;
        g_A[tid*4+2] += v2; g_A[tid*4+3] += v3;
        len[tid] = sqrtf(v0*v0 + v1*v1 + v2*v2 + v3*v3);
    }
    __syncthreads();
    if (last && tid < BB) {
        float mx = -1e30f;
        #pragma unroll
        for (int c = 0; c < NCLS; ++c) mx = fmaxf(mx, len[tid*NCLS + c]);
        float e[NCLS]; float se = 0.f;
        #pragma unroll
        for (int c = 0; c < NCLS; ++c) { e[c] = __expf(len[tid*NCLS + c] - mx); se += e[c]; }
        const float inv = 1.f / se;
        #pragma unroll
        for (int c = 0; c < NCLS; ++c) out[tid*NCLS + c] = e[c] * inv;
    }
}

// ---------------- launch ----------------
extern "C" void kernel_launch(void* const* d_in, const int* in_sizes, int n_in,
                              void* d_out, int out_size) {
    const float* x        = (const float*)d_in[0];
    const float* conv_w   = (const float*)d_in[1];
    const float* conv_b   = (const float*)d_in[2];
    const float* pcaps_w  = (const float*)d_in[3];
    const float* pcaps_b  = (const float*)d_in[4];
    const float* route_W  = (const float*)d_in[5];
    float* out = (float*)d_out;

    cudaFuncSetAttribute(mma_gemm_kernel, cudaFuncAttributeMaxDynamicSharedMemorySize, SMEMB);

    conv1_kernel<<<dim3(C0, BB), 256>>>(x, conv_w, conv_b);
    im2col_split_kernel<<<(int)(((size_t)MPAD*KD)/256), 256>>>();
    wsplit_kernel<<<(int)(((size_t)NN*KD)/256), 256>>>(pcaps_w);
    mma_gemm_kernel<<<dim3(NTILES, MTILES), 256, SMEMB>>>(pcaps_b);
    squash_kernel<<<5408, 256>>>();   // 43264 warps = 32b * 169sp * 8 groups
    uhat_kernel<<<ROUTES, 256>>>(route_W);
    init_kernel<<<(BB*NCLS*OD + 255)/256, 256>>>();
    for (int t = 0; t < 8; ++t) {
        route_reduce_kernel<<<dim3(BB, RCH), 256>>>();
        finalize_kernel<<<1, 512>>>(out, t == 7);
    }
}